// round 2
// baseline (speedup 1.0000x reference)
#include <cuda_runtime.h>
#include <cuda_fp16.h>

#define SEQ   512
#define BATCH 64
#define HID   1024
#define EMB   1024
#define G3    (3*HID)        // 3072
#define RGRID 128            // recurrent CTAs (<= SM count, co-resident)
#define RTHREADS 192         // 6 warps

// ---------------- device scratch (static, no allocation) ----------------
__device__ __half d_Xh [SEQ*BATCH*EMB];        // 64 MB  gathered embeddings [m][k]
__device__ __half d_Wih[G3*EMB];               // 6 MB   W_ih fp16 [n][k]
__device__ __half d_Wr [G3*EMB];               // 6 MB   W_hh rearranged per-CTA blocks
__device__ __half d_gih[(size_t)SEQ*G3*BATCH]; // 201 MB gi fp16 [t][n][b]
__device__ float  d_hf [BATCH*HID];            // h fp32 master [b][n]
__device__ __half d_hh [BATCH*HID];            // h fp16 (MMA input) [b][n]
__device__ float  d_partial[RGRID*192*64];     // 6.3 MB per-CTA partial gh tiles
__device__ unsigned int d_bar;

// ---------------- mma m16n8k16 f16 x f16 -> f32 ----------------
__device__ __forceinline__ void mma16816(float* d, const unsigned* a, const unsigned* b) {
    asm volatile(
        "mma.sync.aligned.m16n8k16.row.col.f32.f16.f16.f32 "
        "{%0,%1,%2,%3}, {%4,%5,%6,%7}, {%8,%9}, {%0,%1,%2,%3};\n"
        : "+f"(d[0]), "+f"(d[1]), "+f"(d[2]), "+f"(d[3])
        : "r"(a[0]), "r"(a[1]), "r"(a[2]), "r"(a[3]), "r"(b[0]), "r"(b[1]));
}

// ---------------- prep kernels ----------------
__global__ void k_convert_wih(const float* __restrict__ W) {
    int n = G3*EMB;
    for (int i = blockIdx.x*blockDim.x + threadIdx.x; i < n; i += gridDim.x*blockDim.x)
        d_Wih[i] = __float2half_rn(W[i]);
}

// W_hh -> per-(CTA,kstep) contiguous blocks: d_Wr[((c*8+ks)*192+row)*16+kk]
// c = tile*8 + s ; row = gate*64 + r ; src = W_hh[gate*1024 + tile*64 + r][s*128 + ks*16 + kk]
__global__ void k_convert_whh(const float* __restrict__ W) {
    int n = G3*EMB;
    for (int i = blockIdx.x*blockDim.x + threadIdx.x; i < n; i += gridDim.x*blockDim.x) {
        int kk  = i & 15;
        int r2  = i >> 4;
        int row = r2 % 192;
        int r3  = r2 / 192;
        int ks  = r3 & 7;
        int c   = r3 >> 3;
        int s = c & 7, tile = c >> 3;
        int gate = row / 64, rr = row % 64;
        int srcRow = gate*1024 + tile*64 + rr;
        int srcK   = s*128 + ks*16 + kk;
        d_Wr[i] = __float2half_rn(W[(size_t)srcRow*EMB + srcK]);
    }
}

__global__ void k_gather(const int* __restrict__ idx, const float* __restrict__ emb) {
    size_t n = (size_t)SEQ*BATCH*EMB;
    for (size_t i = (size_t)blockIdx.x*blockDim.x + threadIdx.x; i < n; i += (size_t)gridDim.x*blockDim.x) {
        int k = (int)(i & (EMB-1));
        int m = (int)(i >> 10);
        d_Xh[i] = __float2half_rn(emb[(size_t)idx[m]*EMB + k]);
    }
}

__global__ void k_init_h(const float* __restrict__ h0) {
    int i = blockIdx.x*blockDim.x + threadIdx.x;
    if (i == 0) d_bar = 0u;
    if (i < BATCH*HID) {
        float v = h0[i];
        d_hf[i] = v;
        d_hh[i] = __float2half_rn(v);
    }
}

// ---------------- gi GEMM: gi[t][n][b] = sum_k W_ih[n][k]*X[t*64+b][k] + b_ih[n] ---------
// CTA tile: 64 (n) x 64 (b, = one t), K stepped by 32, double-buffered smem, HMMA.
__global__ __launch_bounds__(128) void k_gi_gemm(const float* __restrict__ b_ih) {
    __shared__ __half As[2][64*40];   // W rows, padded stride 40 (bank-conflict free)
    __shared__ __half Bs[2][64*40];   // X rows

    const int t   = blockIdx.y;
    const int n0  = blockIdx.x * 64;
    const int tid = threadIdx.x;
    const int lane = tid & 31, w = tid >> 5;
    const int wm = (w & 1) * 32;   // M (n) offset of warp
    const int wn = (w >> 1) * 32;  // N (b) offset of warp
    const int g  = lane >> 2, tg = lane & 3;

    const __half* Aglob = d_Wih + (size_t)n0 * EMB;
    const __half* Bglob = d_Xh  + (size_t)t * 64 * EMB;

    float acc[2][4][4];
#pragma unroll
    for (int mi = 0; mi < 2; mi++)
#pragma unroll
        for (int nf = 0; nf < 4; nf++)
#pragma unroll
            for (int q = 0; q < 4; q++) acc[mi][nf][q] = 0.f;

    // prologue: stage k0=0
#pragma unroll
    for (int j = 0; j < 2; j++) {
        int u = tid + j*128, row = u >> 2, q = u & 3;
        *(uint4*)&As[0][row*40 + q*8] = *(const uint4*)&Aglob[(size_t)row*EMB + q*8];
        *(uint4*)&Bs[0][row*40 + q*8] = *(const uint4*)&Bglob[(size_t)row*EMB + q*8];
    }
    __syncthreads();

    int buf = 0;
    for (int k0 = 0; k0 < EMB; k0 += 32) {
        uint4 pa[2], pb[2];
        const bool more = (k0 + 32 < EMB);
        if (more) {
#pragma unroll
            for (int j = 0; j < 2; j++) {
                int u = tid + j*128, row = u >> 2, q = u & 3;
                pa[j] = *(const uint4*)&Aglob[(size_t)row*EMB + k0 + 32 + q*8];
                pb[j] = *(const uint4*)&Bglob[(size_t)row*EMB + k0 + 32 + q*8];
            }
        }
#pragma unroll
        for (int kk = 0; kk < 32; kk += 16) {
            unsigned a[2][4], b[4][2];
#pragma unroll
            for (int mi = 0; mi < 2; mi++) {
                const __half* base = &As[buf][(wm + mi*16 + g)*40 + kk + 2*tg];
                a[mi][0] = *(const unsigned*)(base);
                a[mi][1] = *(const unsigned*)(base + 8*40);
                a[mi][2] = *(const unsigned*)(base + 8);
                a[mi][3] = *(const unsigned*)(base + 8*40 + 8);
            }
#pragma unroll
            for (int nf = 0; nf < 4; nf++) {
                const __half* base = &Bs[buf][(wn + nf*8 + g)*40 + kk + 2*tg];
                b[nf][0] = *(const unsigned*)(base);
                b[nf][1] = *(const unsigned*)(base + 8);
            }
#pragma unroll
            for (int mi = 0; mi < 2; mi++)
#pragma unroll
                for (int nf = 0; nf < 4; nf++)
                    mma16816(acc[mi][nf], a[mi], b[nf]);
        }
        if (more) {
#pragma unroll
            for (int j = 0; j < 2; j++) {
                int u = tid + j*128, row = u >> 2, q = u & 3;
                *(uint4*)&As[buf^1][row*40 + q*8] = pa[j];
                *(uint4*)&Bs[buf^1][row*40 + q*8] = pb[j];
            }
            __syncthreads();
            buf ^= 1;
        }
    }

    // epilogue: gi fp16 [t][n][b] with b_ih folded in
#pragma unroll
    for (int mi = 0; mi < 2; mi++) {
#pragma unroll
        for (int nf = 0; nf < 4; nf++) {
            int nrow0 = n0 + wm + mi*16 + g;
            int bcol  = wn + nf*8 + 2*tg;
            float bias0 = b_ih[nrow0];
            float bias8 = b_ih[nrow0 + 8];
            __half2 v01 = __floats2half2_rn(acc[mi][nf][0] + bias0, acc[mi][nf][1] + bias0);
            __half2 v23 = __floats2half2_rn(acc[mi][nf][2] + bias8, acc[mi][nf][3] + bias8);
            size_t o0 = ((size_t)t*G3 + nrow0)*64 + bcol;
            *(__half2*)&d_gih[o0]         = v01;
            *(__half2*)&d_gih[o0 + 8*64]  = v23;
        }
    }
}

// ---------------- software grid barrier (all RGRID CTAs co-resident) ----------------
__device__ __forceinline__ void grid_barrier(unsigned target) {
    __syncthreads();
    if (threadIdx.x == 0) {
        __threadfence();
        atomicAdd(&d_bar, 1u);
        while (*((volatile unsigned*)&d_bar) < target * (unsigned)RGRID) {
            __nanosleep(32);
        }
        __threadfence();
    }
    __syncthreads();
}

// ---------------- persistent recurrent kernel ----------------
// phase 1: CTA c = tile*8 + s computes partial gh (192 rows = 3 gates x 64 hid) x 64 batch
//          over K-slice [s*128, s*128+128) with HMMA.
// phase 2: CTA c = tile2*8 + bs2 reduces 8 partials for (64 hid x 8 batch), applies gates,
//          updates h (fp32 master + fp16 copy), writes output step t.
__global__ __launch_bounds__(RTHREADS, 1) void k_recurrent(const float* __restrict__ b_hh,
                                                           float* __restrict__ out) {
    __shared__ __half Ws[2][192*24];   // W block stage, padded stride 24
    __shared__ __half hs[64*136];      // h slice [b][k], padded stride 136

    const int c    = blockIdx.x;
    const int tid  = threadIdx.x;
    const int lane = tid & 31, w = tid >> 5;        // 6 warps, 32 rows each
    const int g = lane >> 2, tg = lane & 3;
    const int wm = w * 32;
    const int s = c & 7;                             // K-slice
    const int k0 = s * 128;
    const int tile2 = c >> 3, bs2 = c & 7;           // phase-2 role
    const __half* Wbase = d_Wr + (size_t)c * (8*192*16);
    float* pbase = d_partial + (size_t)c * (192*64);

    unsigned epoch = 0;

    for (int t = 0; t < SEQ; ++t) {
        // ---- phase 1: load h slice (L2, bypass L1: written by other CTAs) ----
        for (int u = tid; u < 1024; u += RTHREADS) {
            int row = u >> 4, q = u & 15;
            uint4 v = __ldcg((const uint4*)&d_hh[row*HID + k0 + q*8]);
            *(uint4*)&hs[row*136 + q*8] = v;
        }
#pragma unroll
        for (int j = 0; j < 2; j++) {          // stage Ws ks=0
            int uu = tid + j*RTHREADS, row = uu >> 1, p = uu & 1;
            *(uint4*)&Ws[0][row*24 + p*8] = *(const uint4*)&Wbase[(size_t)row*16 + p*8];
        }
        __syncthreads();

        float acc[2][8][4];
#pragma unroll
        for (int mi = 0; mi < 2; mi++)
#pragma unroll
            for (int nf = 0; nf < 8; nf++)
#pragma unroll
                for (int q = 0; q < 4; q++) acc[mi][nf][q] = 0.f;

        int buf = 0;
        for (int ks = 0; ks < 8; ++ks) {
            uint4 pw[2];
            if (ks < 7) {
#pragma unroll
                for (int j = 0; j < 2; j++) {
                    int uu = tid + j*RTHREADS, row = uu >> 1, p = uu & 1;
                    pw[j] = *(const uint4*)&Wbase[((size_t)(ks+1)*192 + row)*16 + p*8];
                }
            }
            unsigned a[2][4];
#pragma unroll
            for (int mi = 0; mi < 2; mi++) {
                const __half* base = &Ws[buf][(wm + mi*16 + g)*24 + 2*tg];
                a[mi][0] = *(const unsigned*)(base);
                a[mi][1] = *(const unsigned*)(base + 8*24);
                a[mi][2] = *(const unsigned*)(base + 8);
                a[mi][3] = *(const unsigned*)(base + 8*24 + 8);
            }
#pragma unroll
            for (int nf = 0; nf < 8; nf++) {
                const __half* hb = &hs[(nf*8 + g)*136 + ks*16 + 2*tg];
                unsigned b[2];
                b[0] = *(const unsigned*)(hb);
                b[1] = *(const unsigned*)(hb + 8);
#pragma unroll
                for (int mi = 0; mi < 2; mi++)
                    mma16816(acc[mi][nf], a[mi], b);
            }
            if (ks < 7) {
#pragma unroll
                for (int j = 0; j < 2; j++) {
                    int uu = tid + j*RTHREADS, row = uu >> 1, p = uu & 1;
                    *(uint4*)&Ws[buf^1][row*24 + p*8] = pw[j];
                }
                __syncthreads();
                buf ^= 1;
            }
        }

        // write partial tile (own region, deterministic)
#pragma unroll
        for (int mi = 0; mi < 2; mi++) {
#pragma unroll
            for (int nf = 0; nf < 8; nf++) {
                int row = wm + mi*16 + g;
                int col = nf*8 + 2*tg;
                *(float2*)&pbase[row*64 + col]     = make_float2(acc[mi][nf][0], acc[mi][nf][1]);
                *(float2*)&pbase[(row+8)*64 + col] = make_float2(acc[mi][nf][2], acc[mi][nf][3]);
            }
        }

        grid_barrier(++epoch);

        // ---- phase 2: reduce + gates ----
        for (int i = tid; i < 512; i += RTHREADS) {
            int nloc = i >> 3, bloc = i & 7;
            int n = tile2*64 + nloc;
            int b = bs2*8 + bloc;
            float rs = 0.f, zs = 0.f, ns = 0.f;
#pragma unroll
            for (int ss = 0; ss < 8; ss++) {
                const float* pp = d_partial + (size_t)(tile2*8 + ss)*(192*64);
                rs += __ldcg(&pp[nloc*64 + b]);
                zs += __ldcg(&pp[(64 + nloc)*64 + b]);
                ns += __ldcg(&pp[(128 + nloc)*64 + b]);
            }
            size_t gbase = (size_t)t * G3 * 64;
            float gir = __half2float(d_gih[gbase + (size_t)n*64 + b]);
            float giz = __half2float(d_gih[gbase + (size_t)(1024 + n)*64 + b]);
            float gin = __half2float(d_gih[gbase + (size_t)(2048 + n)*64 + b]);
            float r  = 1.f / (1.f + __expf(-(gir + rs + b_hh[n])));
            float z  = 1.f / (1.f + __expf(-(giz + zs + b_hh[1024 + n])));
            float nn = tanhf(gin + r * (ns + b_hh[2048 + n]));
            float hold = d_hf[b*HID + n];
            float hnew = (1.f - z) * nn + z * hold;
            d_hf[b*HID + n] = hnew;
            d_hh[b*HID + n] = __float2half_rn(hnew);
            out[((size_t)t*64 + b)*HID + n] = hnew;
        }

        grid_barrier(++epoch);
    }
}

// ---------------- launch ----------------
extern "C" void kernel_launch(void* const* d_in, const int* in_sizes, int n_in,
                              void* d_out, int out_size) {
    (void)in_sizes; (void)n_in; (void)out_size;
    const int*   input  = (const int*)  d_in[0];
    // d_in[1] = input_lengths (unused by reference)
    const float* hidden = (const float*)d_in[2];
    const float* emb    = (const float*)d_in[3];
    const float* W_ih   = (const float*)d_in[4];
    const float* W_hh   = (const float*)d_in[5];
    const float* b_ih   = (const float*)d_in[6];
    const float* b_hh   = (const float*)d_in[7];
    float* out = (float*)d_out;

    k_convert_wih<<<3072, 256>>>(W_ih);
    k_convert_whh<<<3072, 256>>>(W_hh);
    k_gather<<<8192, 256>>>(input, emb);
    k_init_h<<<256, 256>>>(hidden);

    dim3 ggrid(48, 512);
    k_gi_gemm<<<ggrid, 128>>>(b_ih);

    k_recurrent<<<RGRID, RTHREADS>>>(b_hh, out);
}

// round 3
// speedup vs baseline: 1.9200x; 1.9200x over previous
#include <cuda_runtime.h>
#include <cuda_fp16.h>

#define SEQ   512
#define BATCH 64
#define HID   1024
#define EMB   1024
#define G3    (3*HID)        // 3072
#define RGRID 128            // recurrent CTAs (1 per SM, co-resident)
#define RTHR  256            // 8 warps

// ---------------- device scratch (static, no allocation) ----------------
__device__ __half d_Xh [SEQ*BATCH*EMB];        // 64 MB  gathered embeddings [m][k]
__device__ __half d_Wih[G3*EMB];               // 6 MB   W_ih fp16 [n][k]
__device__ __half d_gih[(size_t)SEQ*G3*BATCH]; // 201 MB gi fp16 [t][n][b]
__device__ __half d_hh [BATCH*HID];            // h fp16 [b][n]
__device__ unsigned int d_bar;

// ---------------- mma m16n8k16 f16 x f16 -> f32 ----------------
__device__ __forceinline__ void mma16816(float* d, const unsigned* a, const unsigned* b) {
    asm volatile(
        "mma.sync.aligned.m16n8k16.row.col.f32.f16.f16.f32 "
        "{%0,%1,%2,%3}, {%4,%5,%6,%7}, {%8,%9}, {%0,%1,%2,%3};\n"
        : "+f"(d[0]), "+f"(d[1]), "+f"(d[2]), "+f"(d[3])
        : "r"(a[0]), "r"(a[1]), "r"(a[2]), "r"(a[3]), "r"(b[0]), "r"(b[1]));
}

__device__ __forceinline__ unsigned smaddr(const void* p) {
    return (unsigned)__cvta_generic_to_shared(p);
}

// ---------------- prep kernels ----------------
__global__ void k_convert_wih(const float* __restrict__ W) {
    int n = G3*EMB;
    for (int i = blockIdx.x*blockDim.x + threadIdx.x; i < n; i += gridDim.x*blockDim.x)
        d_Wih[i] = __float2half_rn(W[i]);
}

__global__ void k_gather(const int* __restrict__ idx, const float* __restrict__ emb) {
    size_t n = (size_t)SEQ*BATCH*EMB;
    for (size_t i = (size_t)blockIdx.x*blockDim.x + threadIdx.x; i < n; i += (size_t)gridDim.x*blockDim.x) {
        int k = (int)(i & (EMB-1));
        int m = (int)(i >> 10);
        d_Xh[i] = __float2half_rn(emb[(size_t)idx[m]*EMB + k]);
    }
}

__global__ void k_init_h(const float* __restrict__ h0) {
    int i = blockIdx.x*blockDim.x + threadIdx.x;
    if (i == 0) d_bar = 0u;
    if (i < BATCH*HID)
        d_hh[i] = __float2half_rn(h0[i]);
}

// ---------------- gi GEMM: gi[t][n][b] = sum_k W_ih[n][k]*X[t*64+b][k] + b_ih[n] ---------
// CTA tile: 128 (n) x 64 (b, = one t), K stepped by 32, double-buffered smem, HMMA.
__global__ __launch_bounds__(256) void k_gi_gemm(const float* __restrict__ b_ih) {
    __shared__ __half As[2][128*40];
    __shared__ __half Bs[2][64*40];

    const int t   = blockIdx.y;
    const int n0  = blockIdx.x * 128;
    const int tid = threadIdx.x;
    const int lane = tid & 31, w = tid >> 5;
    const int wm = (w & 3) * 32;   // n offset of warp within 128
    const int wn = (w >> 2) * 32;  // b offset of warp
    const int g  = lane >> 2, tg = lane & 3;

    const __half* Aglob = d_Wih + (size_t)n0 * EMB;
    const __half* Bglob = d_Xh  + (size_t)t * 64 * EMB;

    float acc[2][4][4];
#pragma unroll
    for (int mi = 0; mi < 2; mi++)
#pragma unroll
        for (int nf = 0; nf < 4; nf++)
#pragma unroll
            for (int q = 0; q < 4; q++) acc[mi][nf][q] = 0.f;

    // prologue: stage k0=0
#pragma unroll
    for (int j = 0; j < 2; j++) {
        int u = tid + j*256, row = u >> 2, q = u & 3;
        *(uint4*)&As[0][row*40 + q*8] = *(const uint4*)&Aglob[(size_t)row*EMB + q*8];
    }
    {
        int row = tid >> 2, q = tid & 3;
        *(uint4*)&Bs[0][row*40 + q*8] = *(const uint4*)&Bglob[(size_t)row*EMB + q*8];
    }
    __syncthreads();

    int buf = 0;
    for (int k0 = 0; k0 < EMB; k0 += 32) {
        uint4 pa[2], pb;
        const bool more = (k0 + 32 < EMB);
        if (more) {
#pragma unroll
            for (int j = 0; j < 2; j++) {
                int u = tid + j*256, row = u >> 2, q = u & 3;
                pa[j] = *(const uint4*)&Aglob[(size_t)row*EMB + k0 + 32 + q*8];
            }
            {
                int row = tid >> 2, q = tid & 3;
                pb = *(const uint4*)&Bglob[(size_t)row*EMB + k0 + 32 + q*8];
            }
        }
#pragma unroll
        for (int kk = 0; kk < 32; kk += 16) {
            unsigned a[2][4], b[4][2];
#pragma unroll
            for (int mi = 0; mi < 2; mi++) {
                const __half* base = &As[buf][(wm + mi*16 + g)*40 + kk + 2*tg];
                a[mi][0] = *(const unsigned*)(base);
                a[mi][1] = *(const unsigned*)(base + 8*40);
                a[mi][2] = *(const unsigned*)(base + 8);
                a[mi][3] = *(const unsigned*)(base + 8*40 + 8);
            }
#pragma unroll
            for (int nf = 0; nf < 4; nf++) {
                const __half* base = &Bs[buf][(wn + nf*8 + g)*40 + kk + 2*tg];
                b[nf][0] = *(const unsigned*)(base);
                b[nf][1] = *(const unsigned*)(base + 8);
            }
#pragma unroll
            for (int mi = 0; mi < 2; mi++)
#pragma unroll
                for (int nf = 0; nf < 4; nf++)
                    mma16816(acc[mi][nf], a[mi], b[nf]);
        }
        if (more) {
#pragma unroll
            for (int j = 0; j < 2; j++) {
                int u = tid + j*256, row = u >> 2, q = u & 3;
                *(uint4*)&As[buf^1][row*40 + q*8] = pa[j];
            }
            {
                int row = tid >> 2, q = tid & 3;
                *(uint4*)&Bs[buf^1][row*40 + q*8] = pb;
            }
            __syncthreads();
            buf ^= 1;
        }
    }

    // epilogue: gi fp16 [t][n][b] with b_ih folded in
#pragma unroll
    for (int mi = 0; mi < 2; mi++) {
#pragma unroll
        for (int nf = 0; nf < 4; nf++) {
            int nrow0 = n0 + wm + mi*16 + g;
            int bcol  = wn + nf*8 + 2*tg;
            float bias0 = __ldg(&b_ih[nrow0]);
            float bias8 = __ldg(&b_ih[nrow0 + 8]);
            __half2 v01 = __floats2half2_rn(acc[mi][nf][0] + bias0, acc[mi][nf][1] + bias0);
            __half2 v23 = __floats2half2_rn(acc[mi][nf][2] + bias8, acc[mi][nf][3] + bias8);
            size_t o0 = ((size_t)t*G3 + nrow0)*64 + bcol;
            *(__half2*)&d_gih[o0]         = v01;
            *(__half2*)&d_gih[o0 + 8*64]  = v23;
        }
    }
}

// ---------------- software grid barrier ----------------
__device__ __forceinline__ void grid_barrier(unsigned target) {
    __syncthreads();
    if (threadIdx.x == 0) {
        __threadfence();
        atomicAdd(&d_bar, 1u);
        unsigned goal = target * (unsigned)RGRID;
        unsigned v;
        do {
            asm volatile("ld.global.cg.u32 %0, [%1];" : "=r"(v) : "l"(&d_bar));
            if (v >= goal) break;
            __nanosleep(20);
        } while (true);
        __threadfence();
    }
    __syncthreads();
}

// ---------------- persistent recurrent kernel ----------------
// 128 CTAs x 256 threads. CTA c owns hid rows [c*8, c*8+8) for all 3 gates
// (gh rows: c*8.., 1024+c*8.., 2048+c*8..), all 64 batch, full K=1024.
// Warp w owns K-slice [w*128, w*128+128); W_hh fragments live in registers.
// Output computed transposed: gh^T[b][n24], M=batch(64), N=24, split-K over warps,
// reduced in smem, then gates applied locally. ONE grid barrier per step.
//
// smem layout (dynamic):
//   [w*17408]            per-warp h-slice: 64 rows x 136 halfs (17408 B)
//                        (overlaid after MMA by per-warp 64x24 f32 partials, 6144 B)
//   [139264]             h32 local fp32 h: [g 0..7][b 0..63] (2048 B)
__global__ __launch_bounds__(RTHR, 1) void k_recurrent(const float* __restrict__ hidden,
                                                       const float* __restrict__ W_hh,
                                                       const float* __restrict__ b_hh,
                                                       float* __restrict__ out) {
    extern __shared__ char smem[];
    const int c    = blockIdx.x;
    const int hid0 = c * 8;
    const int tid  = threadIdx.x;
    const int lane = tid & 31, w = tid >> 5;
    const int g = lane >> 2, tg = lane & 3;
    const int kw = w * 128;

    __half* hsw = (__half*)(smem + w*17408);
    float*  h32 = (float*)(smem + 139264);

    // init local fp32 h: h32[gg*64 + b] = hidden[b][hid0+gg]
    for (int i = tid; i < 512; i += RTHR) {
        int gg = i >> 6, b = i & 63;
        h32[i] = hidden[b*HID + hid0 + gg];
    }

    // ---- load W_hh fragments into registers (once) ----
    // Wreg[s][j]: B-fragment for kstep s (k = kw + s*16), ntile j (gate j, col g)
    unsigned Wreg[8][3][2];
#pragma unroll
    for (int s = 0; s < 8; s++) {
#pragma unroll
        for (int j = 0; j < 3; j++) {
            int row = j*1024 + hid0 + g;
            int k0  = kw + s*16 + 2*tg;
            float2 v0 = *(const float2*)&W_hh[(size_t)row*HID + k0];
            float2 v1 = *(const float2*)&W_hh[(size_t)row*HID + k0 + 8];
            __half2 h0 = __floats2half2_rn(v0.x, v0.y);
            __half2 h1 = __floats2half2_rn(v1.x, v1.y);
            Wreg[s][j][0] = *(unsigned*)&h0;
            Wreg[s][j][1] = *(unsigned*)&h1;
        }
    }

    // per-thread gate constants: outputs (b, gg) and (b, gg+1)
    const int b_o  = tid >> 2;
    const int gg_o = (2*tid) & 7;
    const float br0 = b_hh[hid0 + gg_o],        br1 = b_hh[hid0 + gg_o + 1];
    const float bz0 = b_hh[1024 + hid0 + gg_o], bz1 = b_hh[1024 + hid0 + gg_o + 1];
    const float bn0 = b_hh[2048 + hid0 + gg_o], bn1 = b_hh[2048 + hid0 + gg_o + 1];

    // ldmatrix lane address base
    const int r8 = lane & 7, quad = lane >> 3;
    const unsigned lm_base = smaddr(hsw) + (unsigned)(((r8 + (quad & 1)*8)*136 + (quad >> 1)*8) * 2);

    unsigned epoch = 0;
    __syncthreads();

    for (int t = 0; t < SEQ; ++t) {
        // prefetch gi for this thread's two outputs
        const __half* gp = d_gih + (size_t)t * G3 * 64;
        float gir0 = __half2float(gp[(hid0+gg_o)*64 + b_o]);
        float gir1 = __half2float(gp[(hid0+gg_o+1)*64 + b_o]);
        float giz0 = __half2float(gp[(1024+hid0+gg_o)*64 + b_o]);
        float giz1 = __half2float(gp[(1024+hid0+gg_o+1)*64 + b_o]);
        float gin0 = __half2float(gp[(2048+hid0+gg_o)*64 + b_o]);
        float gin1 = __half2float(gp[(2048+hid0+gg_o+1)*64 + b_o]);

        // ---- load this warp's h K-slice into smem (L2 read, written by peers) ----
#pragma unroll
        for (int i = 0; i < 32; i++) {
            int idx = i*32 + lane;
            int row = idx >> 4, q = idx & 15;
            uint4 v = __ldcg((const uint4*)&d_hh[row*HID + kw + q*8]);
            *(uint4*)&hsw[row*136 + q*8] = v;
        }
        __syncwarp();

        // ---- MMA: acc[mt][j] = h[b][k] * W[n][k]^T over this warp's K-slice ----
        float acc[4][3][4];
#pragma unroll
        for (int mt = 0; mt < 4; mt++)
#pragma unroll
            for (int j = 0; j < 3; j++)
#pragma unroll
                for (int q = 0; q < 4; q++) acc[mt][j][q] = 0.f;

#pragma unroll
        for (int s = 0; s < 8; s++) {
#pragma unroll
            for (int mt = 0; mt < 4; mt++) {
                unsigned a[4];
                unsigned addr = lm_base + (unsigned)(mt*4352 + s*32);
                asm volatile("ldmatrix.sync.aligned.m8n8.x4.shared.b16 {%0,%1,%2,%3}, [%4];"
                             : "=r"(a[0]), "=r"(a[1]), "=r"(a[2]), "=r"(a[3]) : "r"(addr));
#pragma unroll
                for (int j = 0; j < 3; j++)
                    mma16816(acc[mt][j], a, Wreg[s][j]);
            }
        }

        // ---- write partials to smem (overlay own h region) ----
        float* redw = (float*)(smem + w*17408);
#pragma unroll
        for (int mt = 0; mt < 4; mt++) {
#pragma unroll
            for (int j = 0; j < 3; j++) {
                int col = j*8 + 2*tg;
                *(float2*)&redw[(mt*16 + g)*24 + col]     = make_float2(acc[mt][j][0], acc[mt][j][1]);
                *(float2*)&redw[(mt*16 + g + 8)*24 + col] = make_float2(acc[mt][j][2], acc[mt][j][3]);
            }
        }
        __syncthreads();

        // ---- reduce 8 warps + gates for outputs (b_o, gg_o), (b_o, gg_o+1) ----
        float rs0 = 0.f, rs1 = 0.f, zs0 = 0.f, zs1 = 0.f, ns0 = 0.f, ns1 = 0.f;
#pragma unroll
        for (int ww = 0; ww < 8; ww++) {
            const float* rw = (const float*)(smem + ww*17408);
            float2 rr = *(const float2*)&rw[b_o*24 + gg_o];
            float2 zz = *(const float2*)&rw[b_o*24 + 8 + gg_o];
            float2 nn = *(const float2*)&rw[b_o*24 + 16 + gg_o];
            rs0 += rr.x; rs1 += rr.y;
            zs0 += zz.x; zs1 += zz.y;
            ns0 += nn.x; ns1 += nn.y;
        }
        float r0 = 1.f / (1.f + __expf(-(gir0 + rs0 + br0)));
        float r1 = 1.f / (1.f + __expf(-(gir1 + rs1 + br1)));
        float z0 = 1.f / (1.f + __expf(-(giz0 + zs0 + bz0)));
        float z1 = 1.f / (1.f + __expf(-(giz1 + zs1 + bz1)));
        float n0 = tanhf(gin0 + r0 * (ns0 + bn0));
        float n1 = tanhf(gin1 + r1 * (ns1 + bn1));
        float h0 = h32[gg_o*64 + b_o];
        float h1 = h32[(gg_o+1)*64 + b_o];
        float hn0 = (1.f - z0) * n0 + z0 * h0;
        float hn1 = (1.f - z1) * n1 + z1 * h1;
        h32[gg_o*64 + b_o]     = hn0;
        h32[(gg_o+1)*64 + b_o] = hn1;

        // global h (fp16) + output
        __half2 hv = __floats2half2_rn(hn0, hn1);
        *(__half2*)&d_hh[b_o*HID + hid0 + gg_o] = hv;
        *(float2*)&out[((size_t)t*64 + b_o)*HID + hid0 + gg_o] = make_float2(hn0, hn1);

        __threadfence();
        grid_barrier(++epoch);
    }
}

// ---------------- launch ----------------
extern "C" void kernel_launch(void* const* d_in, const int* in_sizes, int n_in,
                              void* d_out, int out_size) {
    (void)in_sizes; (void)n_in; (void)out_size;
    const int*   input  = (const int*)  d_in[0];
    const float* hidden = (const float*)d_in[2];
    const float* emb    = (const float*)d_in[3];
    const float* W_ih   = (const float*)d_in[4];
    const float* W_hh   = (const float*)d_in[5];
    const float* b_ih   = (const float*)d_in[6];
    const float* b_hh   = (const float*)d_in[7];
    float* out = (float*)d_out;

    const int RSMEM = 139264 + 2048;
    cudaFuncSetAttribute(k_recurrent, cudaFuncAttributeMaxDynamicSharedMemorySize, RSMEM);

    k_convert_wih<<<3072, 256>>>(W_ih);
    k_gather<<<8192, 256>>>(input, emb);
    k_init_h<<<256, 256>>>(hidden);

    dim3 ggrid(24, 512);
    k_gi_gemm<<<ggrid, 256>>>(b_ih);

    k_recurrent<<<RGRID, RTHR, RSMEM>>>(hidden, W_hh, b_hh, out);
}